// round 15
// baseline (speedup 1.0000x reference)
#include <cuda_runtime.h>
#include <cuda_fp16.h>
#include <math.h>
#include <stdint.h>

// ---------------- problem constants ----------------
#define B_   2
#define N_   4096
#define D_   1024
#define H_   16
#define DH_  64
#define R_   64
#define L_   6
#define FF_  4096
#define INNER_ 1024
#define M_   (B_*N_)        // 8192 rows
#define EPS_ 1e-5f
#define STAB_ 1e-6f
#define NCHUNK_ 32          // kv-sum chunks per (b,h)

// ---------------- scratch (static device globals; allowed) ----------------
__device__ __align__(16) __half g_qkv[M_ * 3 * INNER_];    // [phi_q | phi_k | v], half
__device__ __align__(16) __half g_ff1[M_ * FF_];
__device__ __align__(16) __half g_attnout[M_ * INNER_];
__device__ __align__(16) __half g_ln[M_ * D_];
__device__ __align__(16) float  g_kvpart[B_*H_*NCHUNK_*R_*DH_];
__device__ __align__(16) float  g_kspart[B_*H_*NCHUNK_*R_];
__device__ __align__(16) float  g_kv[B_*H_*R_*DH_];
__device__ __align__(16) float  g_ksum[B_*H_*R_];
// fp16 weights: g_Wqkvp holds combined [Wphi_q | Wphi_k | Wv]
__device__ __align__(16) __half g_Wqkvp[L_*3*INNER_*D_];
__device__ __align__(16) __half g_Woutp[L_*D_*INNER_];
__device__ __align__(16) __half g_W1p  [L_*FF_*D_];
__device__ __align__(16) __half g_W2p  [L_*D_*FF_];

// ---------------- helpers ----------------
__device__ __forceinline__ uint32_t smem_u32(const void* p) {
    uint32_t a;
    asm("{ .reg .u64 t; cvta.to.shared.u64 t, %1; cvt.u32.u64 %0, t; }" : "=r"(a) : "l"(p));
    return a;
}
__device__ __forceinline__ void cp16(uint32_t s, const void* g) {
    asm volatile("cp.async.cg.shared.global [%0], [%1], 16;\n" :: "r"(s), "l"(g));
}
#define LDSM_X4(r, addr) \
    asm volatile("ldmatrix.sync.aligned.m8n8.x4.shared.b16 {%0,%1,%2,%3}, [%4];" \
        : "=r"((r)[0]), "=r"((r)[1]), "=r"((r)[2]), "=r"((r)[3]) : "r"(addr))

// ---------------- FP16 tensor-core GEMM, 128x128 tile, 3-stage pipeline -----
// C[M,Nc] = A[M,K] @ Bw[Nc,K]^T  (+ epilogue)
// EPI: 0=none, 1=relu for col<relu_lim, 2=bias+GELU, 3=bias+residual(fp32).
#define KC    32
#define RSTR  40
#define STAGEB (128 * RSTR * 2)

template<int EPI, bool OUTH>
__global__ __launch_bounds__(256) void gemm_fp16(
    const __half* __restrict__ A, const __half* __restrict__ Bw,
    void* __restrict__ Cv, int M, int Nc, int K,
    const float* __restrict__ bias, const float* __restrict__ resid, int relu_lim)
{
    __shared__ __align__(16) __half sh[3][2][128 * RSTR];
    const uint32_t sbase = smem_u32(&sh[0][0][0]);

    const int tid  = threadIdx.x;
    const int bm0  = blockIdx.y * 128;
    const int bn0  = blockIdx.x * 128;
    const int warp = tid >> 5;
    const int lane = tid & 31;
    const int wm   = warp >> 2;
    const int wn   = warp & 3;
    const int g8   = lane >> 2;
    const int qid  = lane & 3;

    float c[4][4][4];
    #pragma unroll
    for (int mi = 0; mi < 4; mi++)
        #pragma unroll
        for (int ni = 0; ni < 4; ni++)
            #pragma unroll
            for (int j = 0; j < 4; j++) c[mi][ni][j] = 0.0f;

    const int nIter = K / KC;

    auto load_stage = [&](int it, int buf) {
        const int k0 = it * KC;
        uint32_t sA = sbase + buf * 2 * STAGEB;
        uint32_t sB = sA + STAGEB;
        #pragma unroll
        for (int i = 0; i < 2; i++) {
            int f = i * 256 + tid;
            int row = f >> 2, seg = f & 3;
            cp16(sA + (row * RSTR + seg * 8) * 2,
                 &A[(size_t)(bm0 + row) * K + k0 + seg * 8]);
        }
        #pragma unroll
        for (int i = 0; i < 2; i++) {
            int f = i * 256 + tid;
            int row = f >> 2, seg = f & 3;
            cp16(sB + (row * RSTR + seg * 8) * 2,
                 &Bw[(size_t)(bn0 + row) * K + k0 + seg * 8]);
        }
        asm volatile("cp.async.commit_group;\n" ::: "memory");
    };

    load_stage(0, 0);
    if (nIter > 1) load_stage(1, 1);

    for (int it = 0; it < nIter; it++) {
        int buf = it % 3;
        if (it + 1 < nIter) {
            asm volatile("cp.async.wait_group 1;\n" ::: "memory");
        } else {
            asm volatile("cp.async.wait_group 0;\n" ::: "memory");
        }
        __syncthreads();
        // prefetch stage it+2 into buffer last read at iteration it-1 (safe:
        // the barrier above proves all warps completed iteration it-1)
        if (it + 2 < nIter) load_stage(it + 2, (it + 2) % 3);

        uint32_t sA = sbase + buf * 2 * STAGEB;
        uint32_t sB = sA + STAGEB;

        #pragma unroll
        for (int ks = 0; ks < KC; ks += 16) {
            uint32_t af[4][4];
            #pragma unroll
            for (int mi = 0; mi < 4; mi++) {
                int m0 = wm * 64 + mi * 16;
                uint32_t addr = sA + (((m0 + (lane & 15)) * RSTR) + ks + ((lane >> 4) << 3)) * 2;
                LDSM_X4(af[mi], addr);
            }
            uint32_t bf[2][4];
            #pragma unroll
            for (int nb = 0; nb < 2; nb++) {
                int n0 = wn * 32 + nb * 16;
                uint32_t addr = sB + (((n0 + (lane & 7) + ((lane >> 4) << 3)) * RSTR)
                                      + ks + (((lane >> 3) & 1) << 3)) * 2;
                LDSM_X4(bf[nb], addr);
            }
            #pragma unroll
            for (int mi = 0; mi < 4; mi++)
                #pragma unroll
                for (int ni = 0; ni < 4; ni++) {
                    uint32_t b0 = bf[ni >> 1][(ni & 1) * 2];
                    uint32_t b1 = bf[ni >> 1][(ni & 1) * 2 + 1];
                    asm volatile(
                        "mma.sync.aligned.m16n8k16.row.col.f32.f16.f16.f32 "
                        "{%0,%1,%2,%3}, {%4,%5,%6,%7}, {%8,%9}, {%0,%1,%2,%3};\n"
                        : "+f"(c[mi][ni][0]), "+f"(c[mi][ni][1]),
                          "+f"(c[mi][ni][2]), "+f"(c[mi][ni][3])
                        : "r"(af[mi][0]), "r"(af[mi][1]), "r"(af[mi][2]), "r"(af[mi][3]),
                          "r"(b0), "r"(b1));
                }
        }
    }

    // ---- epilogue ----
    #pragma unroll
    for (int mi = 0; mi < 4; mi++) {
        int row0 = bm0 + wm * 64 + mi * 16 + g8;
        int row1 = row0 + 8;
        #pragma unroll
        for (int ni = 0; ni < 4; ni++) {
            int col = bn0 + wn * 32 + ni * 8 + qid * 2;
            float o0 = c[mi][ni][0], o1 = c[mi][ni][1];
            float o2 = c[mi][ni][2], o3 = c[mi][ni][3];
            if (EPI == 1) {
                if (col < relu_lim) {
                    o0 = fmaxf(o0, 0.0f); o1 = fmaxf(o1, 0.0f);
                    o2 = fmaxf(o2, 0.0f); o3 = fmaxf(o3, 0.0f);
                }
            }
            if (EPI >= 2) {
                float b0 = bias[col], b1 = bias[col + 1];
                o0 += b0; o1 += b1; o2 += b0; o3 += b1;
            }
            if (EPI == 2) {
                o0 = 0.5f * o0 * (1.0f + erff(o0 * 0.70710678118654752f));
                o1 = 0.5f * o1 * (1.0f + erff(o1 * 0.70710678118654752f));
                o2 = 0.5f * o2 * (1.0f + erff(o2 * 0.70710678118654752f));
                o3 = 0.5f * o3 * (1.0f + erff(o3 * 0.70710678118654752f));
            }
            if (EPI == 3) {
                float2 r0 = *(const float2*)&resid[(size_t)row0 * Nc + col];
                float2 r1 = *(const float2*)&resid[(size_t)row1 * Nc + col];
                o0 += r0.x; o1 += r0.y; o2 += r1.x; o3 += r1.y;
            }
            if (OUTH) {
                __half* C = (__half*)Cv;
                *(__half2*)&C[(size_t)row0 * Nc + col] = __floats2half2_rn(o0, o1);
                *(__half2*)&C[(size_t)row1 * Nc + col] = __floats2half2_rn(o2, o3);
            } else {
                float* C = (float*)Cv;
                *(float2*)&C[(size_t)row0 * Nc + col] = make_float2(o0, o1);
                *(float2*)&C[(size_t)row1 * Nc + col] = make_float2(o2, o3);
            }
        }
    }
}

// ---------------- weight convert: fp32 -> fp16 ----------------
__global__ __launch_bounds__(256) void wconv_kernel(
    const float* __restrict__ in, __half* __restrict__ out, int n4)
{
    int i = blockIdx.x * 256 + threadIdx.x;
    if (i >= n4) return;
    float4 v = *(const float4*)&in[(size_t)i * 4];
    *(__half2*)&out[(size_t)i * 4]     = __floats2half2_rn(v.x, v.y);
    *(__half2*)&out[(size_t)i * 4 + 2] = __floats2half2_rn(v.z, v.w);
}

// ---------------- combined phi weights: Wphi[c,(h,r)] = sum_d W[(h,d),c]*rf[h,d,r]
__global__ __launch_bounds__(256) void wcomb_kernel(
    const float* __restrict__ Wqkv, const float* __restrict__ rf,
    __half* __restrict__ out)
{
    __shared__ float rfs[64 * 64];     // [d][r]
    __shared__ float wt[64][64];       // [d][c-tile]
    int blk = blockIdx.x;              // 0..191
    int l = blk >> 5, rest = blk & 31;
    int qk = rest >> 4, h = rest & 15;
    int tid = threadIdx.x;

    const float* W   = Wqkv + ((size_t)l * 3 * INNER_ + qk * INNER_ + h * DH_) * D_;
    const float* rfh = rf + ((size_t)(l * H_ + h)) * DH_ * R_;
    __half* o = out + (size_t)l * 3 * INNER_ * D_ + (size_t)(qk * INNER_ + h * R_) * D_;

    #pragma unroll
    for (int i = 0; i < 16; i++) rfs[tid + i * 256] = rfh[tid + i * 256];
    __syncthreads();

    int r  = tid >> 2;
    int j0 = (tid & 3) << 4;
    for (int ct = 0; ct < 16; ct++) {
        #pragma unroll
        for (int i = 0; i < 16; i++) {
            int f = tid + i * 256;
            int d = f >> 6, cc = f & 63;
            wt[d][cc] = W[(size_t)d * D_ + ct * 64 + cc];
        }
        __syncthreads();
        float acc[16];
        #pragma unroll
        for (int j = 0; j < 16; j++) acc[j] = 0.0f;
        for (int d = 0; d < 64; d++) {
            float p = rfs[d * 64 + r];
            #pragma unroll
            for (int j = 0; j < 16; j++) acc[j] = fmaf(p, wt[d][j0 + j], acc[j]);
        }
        #pragma unroll
        for (int j = 0; j < 16; j += 2)
            *(__half2*)&o[(size_t)r * D_ + ct * 64 + j0 + j] =
                __floats2half2_rn(acc[j], acc[j + 1]);
        __syncthreads();
    }
}

// ---------------- embedding ----------------
__global__ __launch_bounds__(256) void embed_kernel(
    const int* __restrict__ tokens, const float* __restrict__ te,
    const float* __restrict__ pe, float* __restrict__ x)
{
    int row = blockIdx.x;
    int tid = threadIdx.x;
    int n = row & (N_ - 1);
    int tok = tokens[row];
    float4 a = *(const float4*)&te[(size_t)tok * D_ + tid * 4];
    float4 p = *(const float4*)&pe[(size_t)n * D_ + tid * 4];
    a.x += p.x; a.y += p.y; a.z += p.z; a.w += p.w;
    *(float4*)&x[(size_t)row * D_ + tid * 4] = a;
}

// ---------------- fused LayerNorm (stats + apply -> fp16) -------------------
__global__ __launch_bounds__(256) void ln_kernel(
    const float* __restrict__ x, const float* __restrict__ lng,
    const float* __restrict__ lnb, __half* __restrict__ h)
{
    __shared__ float red[256];
    int row = blockIdx.x, tid = threadIdx.x;
    float4 v = *(const float4*)&x[(size_t)row * D_ + tid * 4];
    red[tid] = v.x + v.y + v.z + v.w; __syncthreads();
    #pragma unroll
    for (int o = 128; o > 0; o >>= 1) { if (tid < o) red[tid] += red[tid + o]; __syncthreads(); }
    float mu = red[0] * (1.0f / D_);
    __syncthreads();
    float dx = v.x - mu, dy = v.y - mu, dz = v.z - mu, dw = v.w - mu;
    red[tid] = dx*dx + dy*dy + dz*dz + dw*dw; __syncthreads();
    #pragma unroll
    for (int o = 128; o > 0; o >>= 1) { if (tid < o) red[tid] += red[tid + o]; __syncthreads(); }
    float rs = rsqrtf(red[0] * (1.0f / D_) + EPS_);
    float4 gg = *(const float4*)&lng[tid * 4];
    float4 bb = *(const float4*)&lnb[tid * 4];
    __half* hr = h + (size_t)row * D_ + tid * 4;
    *(__half2*)&hr[0] = __floats2half2_rn(dx * rs * gg.x + bb.x, dy * rs * gg.y + bb.y);
    *(__half2*)&hr[2] = __floats2half2_rn(dz * rs * gg.z + bb.z, dw * rs * gg.w + bb.w);
}

// ---------------- kv-sum (phi pre-computed; half2 coalesced loads) ----------
__global__ __launch_bounds__(256) void kvsum_kernel(
    const __half* __restrict__ qkvh,
    float* __restrict__ kvpart, float* __restrict__ kspart)
{
    __shared__ float vsm[8][64];
    __shared__ float phism[8][64];
    int tid = threadIdx.x;
    int bh = blockIdx.x;
    int b = bh >> 4, h = bh & 15;
    int chunk = blockIdx.y;            // 0..31, 128 rows each

    int lrow = tid >> 5;               // 0..7  (load mapping: 1 row / warp)
    int lc2  = (tid & 31) << 1;        // 2 cols / thread -> 128B per warp
    float acc[16];
    #pragma unroll
    for (int j = 0; j < 16; j++) acc[j] = 0.0f;
    int my_r  = tid >> 2;
    int my_d0 = (tid & 3) << 4;
    float kslocal = 0.0f;
    int nbase = chunk * 128;

    for (int gidx = 0; gidx < 16; gidx++) {
        int n = nbase + gidx * 8 + lrow;
        size_t base = ((size_t)(b * N_ + n)) * (3 * INNER_) + h * DH_ + lc2;
        float2 pf = __half22float2(*(const __half2*)&qkvh[base + INNER_]);
        float2 vf = __half22float2(*(const __half2*)&qkvh[base + 2 * INNER_]);
        phism[lrow][lc2] = pf.x; phism[lrow][lc2 + 1] = pf.y;
        vsm[lrow][lc2]   = vf.x; vsm[lrow][lc2 + 1]   = vf.y;
        __syncthreads();
        #pragma unroll
        for (int rr = 0; rr < 8; rr++) {
            float p = phism[rr][my_r];
            kslocal += p;              // identical across the 4 threads sharing my_r
            float4 v0 = *(const float4*)&vsm[rr][my_d0];
            float4 v1 = *(const float4*)&vsm[rr][my_d0 + 4];
            float4 v2 = *(const float4*)&vsm[rr][my_d0 + 8];
            float4 v3 = *(const float4*)&vsm[rr][my_d0 + 12];
            acc[0]  = fmaf(p, v0.x, acc[0]);  acc[1]  = fmaf(p, v0.y, acc[1]);
            acc[2]  = fmaf(p, v0.z, acc[2]);  acc[3]  = fmaf(p, v0.w, acc[3]);
            acc[4]  = fmaf(p, v1.x, acc[4]);  acc[5]  = fmaf(p, v1.y, acc[5]);
            acc[6]  = fmaf(p, v1.z, acc[6]);  acc[7]  = fmaf(p, v1.w, acc[7]);
            acc[8]  = fmaf(p, v2.x, acc[8]);  acc[9]  = fmaf(p, v2.y, acc[9]);
            acc[10] = fmaf(p, v2.z, acc[10]); acc[11] = fmaf(p, v2.w, acc[11]);
            acc[12] = fmaf(p, v3.x, acc[12]); acc[13] = fmaf(p, v3.y, acc[13]);
            acc[14] = fmaf(p, v3.z, acc[14]); acc[15] = fmaf(p, v3.w, acc[15]);
        }
        __syncthreads();
    }

    float* kvp = kvpart + ((size_t)(bh * NCHUNK_ + chunk)) * (R_ * DH_);
    #pragma unroll
    for (int j = 0; j < 16; j++) kvp[my_r * 64 + my_d0 + j] = acc[j];

    if ((tid & 3) == 0)
        kspart[(bh * NCHUNK_ + chunk) * R_ + my_r] = kslocal;
}

__global__ __launch_bounds__(256) void kvreduce_kernel(
    const float* __restrict__ kvpart, const float* __restrict__ kspart,
    float* __restrict__ kv, float* __restrict__ ks)
{
    int bh = blockIdx.x, tid = threadIdx.x;
    for (int i = tid; i < R_ * DH_; i += 256) {
        float s = 0.0f;
        #pragma unroll
        for (int c = 0; c < NCHUNK_; c++)
            s += kvpart[((size_t)(bh * NCHUNK_ + c)) * (R_ * DH_) + i];
        kv[(size_t)bh * (R_ * DH_) + i] = s;
    }
    if (tid < 64) {
        float s = 0.0f;
        #pragma unroll
        for (int c = 0; c < NCHUNK_; c++) s += kspart[(bh * NCHUNK_ + c) * R_ + tid];
        ks[bh * R_ + tid] = s;
    }
}

// ---------------- attention out (phi pre-computed; half2 loads) -------------
__global__ __launch_bounds__(256) void attnout_kernel(
    const __half* __restrict__ qkvh,
    const float* __restrict__ kv, const float* __restrict__ ksum,
    __half* __restrict__ out)
{
    __shared__ float kvT[64 * 68];
    __shared__ float kssm[R_];
    __shared__ float phism[8][64];
    int tid = threadIdx.x;
    int bh = blockIdx.x;
    int b = bh >> 4, h = bh & 15;
    int tile = blockIdx.y;

    int prow = tid >> 6, pr = tid & 63;
    int lrow = tid >> 5, lc2 = (tid & 31) << 1;
    const float* kvg = kv + (size_t)bh * (R_ * DH_);
    for (int i = tid; i < R_ * DH_; i += 256) {
        int r = i >> 6, d = i & 63;
        kvT[d * 68 + r] = kvg[i];
    }
    if (tid < 64) kssm[tid] = ksum[bh * R_ + tid];
    __syncthreads();

    int nbase = tile * 128;
    for (int gidx = 0; gidx < 16; gidx++) {
        int nl = nbase + gidx * 8 + lrow;
        size_t lbase = ((size_t)(b * N_ + nl)) * (3 * INNER_) + h * DH_ + lc2;
        float2 pf = __half22float2(*(const __half2*)&qkvh[lbase]);
        phism[lrow][lc2] = pf.x; phism[lrow][lc2 + 1] = pf.y;
        __syncthreads();
        int n0 = nbase + gidx * 8 + prow;
        float a0 = 0.0f, a1 = 0.0f, z0 = 0.0f, z1 = 0.0f;
        #pragma unroll
        for (int rc = 0; rc < 16; rc++) {
            float4 p0 = *(const float4*)&phism[prow    ][rc * 4];
            float4 p1 = *(const float4*)&phism[prow + 4][rc * 4];
            float4 kk = *(const float4*)&kvT[pr * 68 + rc * 4];
            float4 ss = *(const float4*)&kssm[rc * 4];
            a0 = fmaf(p0.x, kk.x, a0); a0 = fmaf(p0.y, kk.y, a0);
            a0 = fmaf(p0.z, kk.z, a0); a0 = fmaf(p0.w, kk.w, a0);
            z0 = fmaf(p0.x, ss.x, z0); z0 = fmaf(p0.y, ss.y, z0);
            z0 = fmaf(p0.z, ss.z, z0); z0 = fmaf(p0.w, ss.w, z0);
            a1 = fmaf(p1.x, kk.x, a1); a1 = fmaf(p1.y, kk.y, a1);
            a1 = fmaf(p1.z, kk.z, a1); a1 = fmaf(p1.w, kk.w, a1);
            z1 = fmaf(p1.x, ss.x, z1); z1 = fmaf(p1.y, ss.y, z1);
            z1 = fmaf(p1.z, ss.z, z1); z1 = fmaf(p1.w, ss.w, z1);
        }
        out[((size_t)(b * N_ + n0    )) * INNER_ + h * DH_ + pr] = __float2half_rn(a0 / (z0 + STAB_));
        out[((size_t)(b * N_ + n0 + 4)) * INNER_ + h * DH_ + pr] = __float2half_rn(a1 / (z1 + STAB_));
        __syncthreads();
    }
}

// ---------------- host driver ----------------
extern "C" void kernel_launch(void* const* d_in, const int* in_sizes, int n_in,
                              void* d_out, int out_size)
{
    const int*   tokens  = (const int*)  d_in[0];
    const float* tok_emb = (const float*)d_in[1];
    const float* pos_emb = (const float*)d_in[2];
    const float* Wqkv    = (const float*)d_in[3];
    const float* Wout    = (const float*)d_in[4];
    const float* bout    = (const float*)d_in[5];
    const float* ln1g    = (const float*)d_in[6];
    const float* ln1b    = (const float*)d_in[7];
    const float* ln2g    = (const float*)d_in[8];
    const float* ln2b    = (const float*)d_in[9];
    const float* W1      = (const float*)d_in[10];
    const float* b1      = (const float*)d_in[11];
    const float* W2      = (const float*)d_in[12];
    const float* b2      = (const float*)d_in[13];
    const float* rf      = (const float*)d_in[14];
    float* x = (float*)d_out;

    float *kvpart, *kspart, *kv, *ksum;
    __half *qkv, *ff1, *attnout, *ln, *Wqkvp, *Woutp, *W1p, *W2p;
    cudaGetSymbolAddress((void**)&qkv,     g_qkv);
    cudaGetSymbolAddress((void**)&ff1,     g_ff1);
    cudaGetSymbolAddress((void**)&attnout, g_attnout);
    cudaGetSymbolAddress((void**)&ln,      g_ln);
    cudaGetSymbolAddress((void**)&kvpart,  g_kvpart);
    cudaGetSymbolAddress((void**)&kspart,  g_kspart);
    cudaGetSymbolAddress((void**)&kv,      g_kv);
    cudaGetSymbolAddress((void**)&ksum,    g_ksum);
    cudaGetSymbolAddress((void**)&Wqkvp,   g_Wqkvp);
    cudaGetSymbolAddress((void**)&Woutp,   g_Woutp);
    cudaGetSymbolAddress((void**)&W1p,     g_W1p);
    cudaGetSymbolAddress((void**)&W2p,     g_W2p);

    // weight prep: combined phi weights (q,k) + fp16 conversions (v + rest)
    wcomb_kernel<<<L_ * 2 * H_, 256>>>(Wqkv, rf, Wqkvp);
    for (int l = 0; l < L_; l++) {
        int n4 = INNER_ * D_ / 4;
        wconv_kernel<<<(n4 + 255) / 256, 256>>>(
            Wqkv  + (size_t)l * 3 * INNER_ * D_ + 2 * (size_t)INNER_ * D_,
            Wqkvp + (size_t)l * 3 * INNER_ * D_ + 2 * (size_t)INNER_ * D_, n4);
    }
    {
        int n4;
        n4 = L_*D_*INNER_ / 4; wconv_kernel<<<(n4+255)/256, 256>>>(Wout, Woutp, n4);
        n4 = L_*FF_*D_    / 4; wconv_kernel<<<(n4+255)/256, 256>>>(W1,   W1p,   n4);
        n4 = L_*D_*FF_    / 4; wconv_kernel<<<(n4+255)/256, 256>>>(W2,   W2p,   n4);
    }

    embed_kernel<<<M_, 256>>>(tokens, tok_emb, pos_emb, x);

    for (int l = 0; l < L_; l++) {
        const __half* Wqkv_l = Wqkvp + (size_t)l * 3 * INNER_ * D_;
        const __half* Wout_l = Woutp + (size_t)l * D_ * INNER_;
        const float* bout_l = bout + (size_t)l * D_;
        const float* ln1g_l = ln1g + (size_t)l * D_;
        const float* ln1b_l = ln1b + (size_t)l * D_;
        const float* ln2g_l = ln2g + (size_t)l * D_;
        const float* ln2b_l = ln2b + (size_t)l * D_;
        const __half* W1_l  = W1p  + (size_t)l * FF_ * D_;
        const float* b1_l   = b1   + (size_t)l * FF_;
        const __half* W2_l  = W2p  + (size_t)l * D_ * FF_;
        const float* b2_l   = b2   + (size_t)l * D_;

        // --- attention block ---
        ln_kernel<<<M_, 256>>>(x, ln1g_l, ln1b_l, ln);
        gemm_fp16<1, true><<<dim3(3 * INNER_ / 128, M_ / 128), 256>>>(
            ln, Wqkv_l, qkv, M_, 3 * INNER_, D_, nullptr, nullptr, 2 * INNER_);
        kvsum_kernel<<<dim3(B_ * H_, NCHUNK_), 256>>>(qkv, kvpart, kspart);
        kvreduce_kernel<<<B_ * H_, 256>>>(kvpart, kspart, kv, ksum);
        attnout_kernel<<<dim3(B_ * H_, N_ / 128), 256>>>(qkv, kv, ksum, attnout);
        gemm_fp16<3, false><<<dim3(D_ / 128, M_ / 128), 256>>>(
            attnout, Wout_l, x, M_, D_, INNER_, bout_l, x, 0);

        // --- FFN block ---
        ln_kernel<<<M_, 256>>>(x, ln2g_l, ln2b_l, ln);
        gemm_fp16<2, true><<<dim3(FF_ / 128, M_ / 128), 256>>>(
            ln, W1_l, ff1, M_, FF_, D_, b1_l, nullptr, 0);
        gemm_fp16<3, false><<<dim3(D_ / 128, M_ / 128), 256>>>(
            ff1, W2_l, x, M_, D_, FF_, b2_l, x, 0);
    }
}

// round 16
// speedup vs baseline: 1.1799x; 1.1799x over previous
#include <cuda_runtime.h>
#include <cuda_fp16.h>
#include <math.h>
#include <stdint.h>

// ---------------- problem constants ----------------
#define B_   2
#define N_   4096
#define D_   1024
#define H_   16
#define DH_  64
#define R_   64
#define L_   6
#define FF_  4096
#define INNER_ 1024
#define M_   (B_*N_)        // 8192 rows
#define EPS_ 1e-5f
#define STAB_ 1e-6f
#define NCHUNK_ 32          // kv-sum chunks per (b,h)

// ---------------- scratch (static device globals; allowed) ----------------
__device__ __align__(16) __half g_qkv[M_ * 3 * INNER_];    // [phi_q | phi_k | v], half
__device__ __align__(16) __half g_ff1[M_ * FF_];
__device__ __align__(16) __half g_attnout[M_ * INNER_];
__device__ __align__(16) __half g_ln[M_ * D_];
__device__ __align__(16) float  g_kvpart[B_*H_*NCHUNK_*R_*DH_];
__device__ __align__(16) float  g_kspart[B_*H_*NCHUNK_*R_];
__device__ __align__(16) float  g_kv[B_*H_*R_*DH_];
__device__ __align__(16) float  g_ksum[B_*H_*R_];
// fp16 weights: g_Wqkvp holds combined [Wphi_q | Wphi_k | Wv]
__device__ __align__(16) __half g_Wqkvp[L_*3*INNER_*D_];
__device__ __align__(16) __half g_Woutp[L_*D_*INNER_];
__device__ __align__(16) __half g_W1p  [L_*FF_*D_];
__device__ __align__(16) __half g_W2p  [L_*D_*FF_];

// ---------------- helpers ----------------
__device__ __forceinline__ uint32_t smem_u32(const void* p) {
    uint32_t a;
    asm("{ .reg .u64 t; cvta.to.shared.u64 t, %1; cvt.u32.u64 %0, t; }" : "=r"(a) : "l"(p));
    return a;
}
__device__ __forceinline__ void cp16(uint32_t s, const void* g) {
    asm volatile("cp.async.cg.shared.global [%0], [%1], 16;\n" :: "r"(s), "l"(g));
}
#define LDSM_X4(r, addr) \
    asm volatile("ldmatrix.sync.aligned.m8n8.x4.shared.b16 {%0,%1,%2,%3}, [%4];" \
        : "=r"((r)[0]), "=r"((r)[1]), "=r"((r)[2]), "=r"((r)[3]) : "r"(addr))

// ---------------- FP16 tensor-core GEMM, 128x128 tile, k-chunk 64 -----------
// C[M,Nc] = A[M,K] @ Bw[Nc,K]^T  (+ epilogue)
// EPI: 0=none, 1=relu for col<relu_lim, 2=bias+GELU, 3=bias+residual(fp32).
// 2-stage double buffer (round-14 order), KC=64 halves per stage.
#define KC    64
#define RSTR  72          // row stride in halves (144B); 144/16=9 coprime 8 -> conflict-free
#define STAGEB (128 * RSTR * 2)          // bytes per tile stage (18432)
#define SMEM_GEMM (2 * 2 * STAGEB)       // 73728 bytes

template<int EPI, bool OUTH>
__global__ __launch_bounds__(256) void gemm_fp16(
    const __half* __restrict__ A, const __half* __restrict__ Bw,
    void* __restrict__ Cv, int M, int Nc, int K,
    const float* __restrict__ bias, const float* __restrict__ resid, int relu_lim)
{
    extern __shared__ __align__(16) __half sh[];
    const uint32_t sbase = smem_u32(&sh[0]);

    const int tid  = threadIdx.x;
    const int bm0  = blockIdx.y * 128;
    const int bn0  = blockIdx.x * 128;
    const int warp = tid >> 5;
    const int lane = tid & 31;
    const int wm   = warp >> 2;
    const int wn   = warp & 3;
    const int g8   = lane >> 2;
    const int qid  = lane & 3;

    float c[4][4][4];
    #pragma unroll
    for (int mi = 0; mi < 4; mi++)
        #pragma unroll
        for (int ni = 0; ni < 4; ni++)
            #pragma unroll
            for (int j = 0; j < 4; j++) c[mi][ni][j] = 0.0f;

    const int nIter = K / KC;

    auto load_stage = [&](int it, int buf) {
        const int k0 = it * KC;
        uint32_t sA = sbase + buf * 2 * STAGEB;
        uint32_t sB = sA + STAGEB;
        #pragma unroll
        for (int i = 0; i < 4; i++) {
            int f = i * 256 + tid;          // 0..1023
            int row = f >> 3, seg = f & 7;  // 8 x 16B segments per 128B row
            cp16(sA + (row * RSTR + seg * 8) * 2,
                 &A[(size_t)(bm0 + row) * K + k0 + seg * 8]);
        }
        #pragma unroll
        for (int i = 0; i < 4; i++) {
            int f = i * 256 + tid;
            int row = f >> 3, seg = f & 7;
            cp16(sB + (row * RSTR + seg * 8) * 2,
                 &Bw[(size_t)(bn0 + row) * K + k0 + seg * 8]);
        }
        asm volatile("cp.async.commit_group;\n" ::: "memory");
    };

    load_stage(0, 0);

    for (int it = 0; it < nIter; it++) {
        int buf = it & 1;
        if (it + 1 < nIter) {
            load_stage(it + 1, buf ^ 1);
            asm volatile("cp.async.wait_group 1;\n" ::: "memory");
        } else {
            asm volatile("cp.async.wait_group 0;\n" ::: "memory");
        }
        __syncthreads();

        uint32_t sA = sbase + buf * 2 * STAGEB;
        uint32_t sB = sA + STAGEB;

        #pragma unroll
        for (int ks = 0; ks < KC; ks += 16) {
            uint32_t af[4][4];
            #pragma unroll
            for (int mi = 0; mi < 4; mi++) {
                int m0 = wm * 64 + mi * 16;
                uint32_t addr = sA + (((m0 + (lane & 15)) * RSTR) + ks + ((lane >> 4) << 3)) * 2;
                LDSM_X4(af[mi], addr);
            }
            uint32_t bf[2][4];
            #pragma unroll
            for (int nb = 0; nb < 2; nb++) {
                int n0 = wn * 32 + nb * 16;
                uint32_t addr = sB + (((n0 + (lane & 7) + ((lane >> 4) << 3)) * RSTR)
                                      + ks + (((lane >> 3) & 1) << 3)) * 2;
                LDSM_X4(bf[nb], addr);
            }
            #pragma unroll
            for (int mi = 0; mi < 4; mi++)
                #pragma unroll
                for (int ni = 0; ni < 4; ni++) {
                    uint32_t b0 = bf[ni >> 1][(ni & 1) * 2];
                    uint32_t b1 = bf[ni >> 1][(ni & 1) * 2 + 1];
                    asm volatile(
                        "mma.sync.aligned.m16n8k16.row.col.f32.f16.f16.f32 "
                        "{%0,%1,%2,%3}, {%4,%5,%6,%7}, {%8,%9}, {%0,%1,%2,%3};\n"
                        : "+f"(c[mi][ni][0]), "+f"(c[mi][ni][1]),
                          "+f"(c[mi][ni][2]), "+f"(c[mi][ni][3])
                        : "r"(af[mi][0]), "r"(af[mi][1]), "r"(af[mi][2]), "r"(af[mi][3]),
                          "r"(b0), "r"(b1));
                }
        }
        __syncthreads();
    }

    // ---- epilogue ----
    #pragma unroll
    for (int mi = 0; mi < 4; mi++) {
        int row0 = bm0 + wm * 64 + mi * 16 + g8;
        int row1 = row0 + 8;
        #pragma unroll
        for (int ni = 0; ni < 4; ni++) {
            int col = bn0 + wn * 32 + ni * 8 + qid * 2;
            float o0 = c[mi][ni][0], o1 = c[mi][ni][1];
            float o2 = c[mi][ni][2], o3 = c[mi][ni][3];
            if (EPI == 1) {
                if (col < relu_lim) {
                    o0 = fmaxf(o0, 0.0f); o1 = fmaxf(o1, 0.0f);
                    o2 = fmaxf(o2, 0.0f); o3 = fmaxf(o3, 0.0f);
                }
            }
            if (EPI >= 2) {
                float b0 = bias[col], b1 = bias[col + 1];
                o0 += b0; o1 += b1; o2 += b0; o3 += b1;
            }
            if (EPI == 2) {
                o0 = 0.5f * o0 * (1.0f + erff(o0 * 0.70710678118654752f));
                o1 = 0.5f * o1 * (1.0f + erff(o1 * 0.70710678118654752f));
                o2 = 0.5f * o2 * (1.0f + erff(o2 * 0.70710678118654752f));
                o3 = 0.5f * o3 * (1.0f + erff(o3 * 0.70710678118654752f));
            }
            if (EPI == 3) {
                float2 r0 = *(const float2*)&resid[(size_t)row0 * Nc + col];
                float2 r1 = *(const float2*)&resid[(size_t)row1 * Nc + col];
                o0 += r0.x; o1 += r0.y; o2 += r1.x; o3 += r1.y;
            }
            if (OUTH) {
                __half* C = (__half*)Cv;
                *(__half2*)&C[(size_t)row0 * Nc + col] = __floats2half2_rn(o0, o1);
                *(__half2*)&C[(size_t)row1 * Nc + col] = __floats2half2_rn(o2, o3);
            } else {
                float* C = (float*)Cv;
                *(float2*)&C[(size_t)row0 * Nc + col] = make_float2(o0, o1);
                *(float2*)&C[(size_t)row1 * Nc + col] = make_float2(o2, o3);
            }
        }
    }
}

// ---------------- weight convert: fp32 -> fp16 ----------------
__global__ __launch_bounds__(256) void wconv_kernel(
    const float* __restrict__ in, __half* __restrict__ out, int n4)
{
    int i = blockIdx.x * 256 + threadIdx.x;
    if (i >= n4) return;
    float4 v = *(const float4*)&in[(size_t)i * 4];
    *(__half2*)&out[(size_t)i * 4]     = __floats2half2_rn(v.x, v.y);
    *(__half2*)&out[(size_t)i * 4 + 2] = __floats2half2_rn(v.z, v.w);
}

// ---------------- combined phi weights: Wphi[c,(h,r)] = sum_d W[(h,d),c]*rf[h,d,r]
__global__ __launch_bounds__(256) void wcomb_kernel(
    const float* __restrict__ Wqkv, const float* __restrict__ rf,
    __half* __restrict__ out)
{
    __shared__ float rfs[64 * 64];     // [d][r]
    __shared__ float wt[64][64];       // [d][c-tile]
    int blk = blockIdx.x;              // 0..191
    int l = blk >> 5, rest = blk & 31;
    int qk = rest >> 4, h = rest & 15;
    int tid = threadIdx.x;

    const float* W   = Wqkv + ((size_t)l * 3 * INNER_ + qk * INNER_ + h * DH_) * D_;
    const float* rfh = rf + ((size_t)(l * H_ + h)) * DH_ * R_;
    __half* o = out + (size_t)l * 3 * INNER_ * D_ + (size_t)(qk * INNER_ + h * R_) * D_;

    #pragma unroll
    for (int i = 0; i < 16; i++) rfs[tid + i * 256] = rfh[tid + i * 256];
    __syncthreads();

    int r  = tid >> 2;
    int j0 = (tid & 3) << 4;
    for (int ct = 0; ct < 16; ct++) {
        #pragma unroll
        for (int i = 0; i < 16; i++) {
            int f = tid + i * 256;
            int d = f >> 6, cc = f & 63;
            wt[d][cc] = W[(size_t)d * D_ + ct * 64 + cc];
        }
        __syncthreads();
        float acc[16];
        #pragma unroll
        for (int j = 0; j < 16; j++) acc[j] = 0.0f;
        for (int d = 0; d < 64; d++) {
            float p = rfs[d * 64 + r];
            #pragma unroll
            for (int j = 0; j < 16; j++) acc[j] = fmaf(p, wt[d][j0 + j], acc[j]);
        }
        #pragma unroll
        for (int j = 0; j < 16; j += 2)
            *(__half2*)&o[(size_t)r * D_ + ct * 64 + j0 + j] =
                __floats2half2_rn(acc[j], acc[j + 1]);
        __syncthreads();
    }
}

// ---------------- embedding ----------------
__global__ __launch_bounds__(256) void embed_kernel(
    const int* __restrict__ tokens, const float* __restrict__ te,
    const float* __restrict__ pe, float* __restrict__ x)
{
    int row = blockIdx.x;
    int tid = threadIdx.x;
    int n = row & (N_ - 1);
    int tok = tokens[row];
    float4 a = *(const float4*)&te[(size_t)tok * D_ + tid * 4];
    float4 p = *(const float4*)&pe[(size_t)n * D_ + tid * 4];
    a.x += p.x; a.y += p.y; a.z += p.z; a.w += p.w;
    *(float4*)&x[(size_t)row * D_ + tid * 4] = a;
}

// ---------------- fused LayerNorm (stats + apply -> fp16) -------------------
__global__ __launch_bounds__(256) void ln_kernel(
    const float* __restrict__ x, const float* __restrict__ lng,
    const float* __restrict__ lnb, __half* __restrict__ h)
{
    __shared__ float red[256];
    int row = blockIdx.x, tid = threadIdx.x;
    float4 v = *(const float4*)&x[(size_t)row * D_ + tid * 4];
    red[tid] = v.x + v.y + v.z + v.w; __syncthreads();
    #pragma unroll
    for (int o = 128; o > 0; o >>= 1) { if (tid < o) red[tid] += red[tid + o]; __syncthreads(); }
    float mu = red[0] * (1.0f / D_);
    __syncthreads();
    float dx = v.x - mu, dy = v.y - mu, dz = v.z - mu, dw = v.w - mu;
    red[tid] = dx*dx + dy*dy + dz*dz + dw*dw; __syncthreads();
    #pragma unroll
    for (int o = 128; o > 0; o >>= 1) { if (tid < o) red[tid] += red[tid + o]; __syncthreads(); }
    float rs = rsqrtf(red[0] * (1.0f / D_) + EPS_);
    float4 gg = *(const float4*)&lng[tid * 4];
    float4 bb = *(const float4*)&lnb[tid * 4];
    __half* hr = h + (size_t)row * D_ + tid * 4;
    *(__half2*)&hr[0] = __floats2half2_rn(dx * rs * gg.x + bb.x, dy * rs * gg.y + bb.y);
    *(__half2*)&hr[2] = __floats2half2_rn(dz * rs * gg.z + bb.z, dw * rs * gg.w + bb.w);
}

// ---------------- kv-sum (round-14 exact structure) -------------------------
__global__ __launch_bounds__(256) void kvsum_kernel(
    const __half* __restrict__ qkvh,
    float* __restrict__ kvpart, float* __restrict__ kspart)
{
    __shared__ float vsm[8][64];
    __shared__ float phism[8][64];
    int tid = threadIdx.x;
    int bh = blockIdx.x;
    int b = bh >> 4, h = bh & 15;
    int chunk = blockIdx.y;            // 0..31, 128 rows each

    int prow = tid >> 6, pr = tid & 63;
    float acc[16];
    #pragma unroll
    for (int j = 0; j < 16; j++) acc[j] = 0.0f;
    int my_r  = tid >> 2;
    int my_d0 = (tid & 3) << 4;
    float kslocal = 0.0f;
    int nbase = chunk * 128;

    for (int gidx = 0; gidx < 16; gidx++) {
        int n0 = nbase + gidx * 8 + prow;
        size_t base0 = ((size_t)(b * N_ + n0)) * (3 * INNER_) + h * DH_;
        size_t base1 = base0 + (size_t)4 * (3 * INNER_);
        float p0 = __half2float(qkvh[base0 + INNER_ + pr]);
        float p1 = __half2float(qkvh[base1 + INNER_ + pr]);
        phism[prow    ][pr] = p0;
        phism[prow + 4][pr] = p1;
        vsm[prow    ][pr] = __half2float(qkvh[base0 + 2 * INNER_ + pr]);
        vsm[prow + 4][pr] = __half2float(qkvh[base1 + 2 * INNER_ + pr]);
        kslocal += p0 + p1;
        __syncthreads();
        #pragma unroll
        for (int rr = 0; rr < 8; rr++) {
            float p = phism[rr][my_r];
            float4 v0 = *(const float4*)&vsm[rr][my_d0];
            float4 v1 = *(const float4*)&vsm[rr][my_d0 + 4];
            float4 v2 = *(const float4*)&vsm[rr][my_d0 + 8];
            float4 v3 = *(const float4*)&vsm[rr][my_d0 + 12];
            acc[0]  = fmaf(p, v0.x, acc[0]);  acc[1]  = fmaf(p, v0.y, acc[1]);
            acc[2]  = fmaf(p, v0.z, acc[2]);  acc[3]  = fmaf(p, v0.w, acc[3]);
            acc[4]  = fmaf(p, v1.x, acc[4]);  acc[5]  = fmaf(p, v1.y, acc[5]);
            acc[6]  = fmaf(p, v1.z, acc[6]);  acc[7]  = fmaf(p, v1.w, acc[7]);
            acc[8]  = fmaf(p, v2.x, acc[8]);  acc[9]  = fmaf(p, v2.y, acc[9]);
            acc[10] = fmaf(p, v2.z, acc[10]); acc[11] = fmaf(p, v2.w, acc[11]);
            acc[12] = fmaf(p, v3.x, acc[12]); acc[13] = fmaf(p, v3.y, acc[13]);
            acc[14] = fmaf(p, v3.z, acc[14]); acc[15] = fmaf(p, v3.w, acc[15]);
        }
        __syncthreads();
    }

    float* kvp = kvpart + ((size_t)(bh * NCHUNK_ + chunk)) * (R_ * DH_);
    #pragma unroll
    for (int j = 0; j < 16; j++) kvp[my_r * 64 + my_d0 + j] = acc[j];

    phism[prow][pr] = kslocal;
    __syncthreads();
    if (tid < 64) {
        float s = phism[0][tid] + phism[1][tid] + phism[2][tid] + phism[3][tid];
        kspart[(bh * NCHUNK_ + chunk) * R_ + tid] = s;
    }
}

__global__ __launch_bounds__(256) void kvreduce_kernel(
    const float* __restrict__ kvpart, const float* __restrict__ kspart,
    float* __restrict__ kv, float* __restrict__ ks)
{
    int bh = blockIdx.x, tid = threadIdx.x;
    for (int i = tid; i < R_ * DH_; i += 256) {
        float s = 0.0f;
        #pragma unroll
        for (int c = 0; c < NCHUNK_; c++)
            s += kvpart[((size_t)(bh * NCHUNK_ + c)) * (R_ * DH_) + i];
        kv[(size_t)bh * (R_ * DH_) + i] = s;
    }
    if (tid < 64) {
        float s = 0.0f;
        #pragma unroll
        for (int c = 0; c < NCHUNK_; c++) s += kspart[(bh * NCHUNK_ + c) * R_ + tid];
        ks[bh * R_ + tid] = s;
    }
}

// ---------------- attention out (round-14 exact structure) ------------------
__global__ __launch_bounds__(256) void attnout_kernel(
    const __half* __restrict__ qkvh,
    const float* __restrict__ kv, const float* __restrict__ ksum,
    __half* __restrict__ out)
{
    __shared__ float kvT[64 * 68];
    __shared__ float kssm[R_];
    __shared__ float phism[8][64];
    int tid = threadIdx.x;
    int bh = blockIdx.x;
    int b = bh >> 4, h = bh & 15;
    int tile = blockIdx.y;

    int prow = tid >> 6, pr = tid & 63;
    const float* kvg = kv + (size_t)bh * (R_ * DH_);
    for (int i = tid; i < R_ * DH_; i += 256) {
        int r = i >> 6, d = i & 63;
        kvT[d * 68 + r] = kvg[i];
    }
    if (tid < 64) kssm[tid] = ksum[bh * R_ + tid];
    __syncthreads();

    int nbase = tile * 128;
    for (int gidx = 0; gidx < 16; gidx++) {
        int n0 = nbase + gidx * 8 + prow;
        size_t base0 = ((size_t)(b * N_ + n0)) * (3 * INNER_) + h * DH_;
        size_t base1 = base0 + (size_t)4 * (3 * INNER_);
        phism[prow    ][pr] = __half2float(qkvh[base0 + pr]);
        phism[prow + 4][pr] = __half2float(qkvh[base1 + pr]);
        __syncthreads();
        float a0 = 0.0f, a1 = 0.0f, z0 = 0.0f, z1 = 0.0f;
        #pragma unroll
        for (int rc = 0; rc < 16; rc++) {
            float4 p0 = *(const float4*)&phism[prow    ][rc * 4];
            float4 p1 = *(const float4*)&phism[prow + 4][rc * 4];
            float4 kk = *(const float4*)&kvT[pr * 68 + rc * 4];
            float4 ss = *(const float4*)&kssm[rc * 4];
            a0 = fmaf(p0.x, kk.x, a0); a0 = fmaf(p0.y, kk.y, a0);
            a0 = fmaf(p0.z, kk.z, a0); a0 = fmaf(p0.w, kk.w, a0);
            z0 = fmaf(p0.x, ss.x, z0); z0 = fmaf(p0.y, ss.y, z0);
            z0 = fmaf(p0.z, ss.z, z0); z0 = fmaf(p0.w, ss.w, z0);
            a1 = fmaf(p1.x, kk.x, a1); a1 = fmaf(p1.y, kk.y, a1);
            a1 = fmaf(p1.z, kk.z, a1); a1 = fmaf(p1.w, kk.w, a1);
            z1 = fmaf(p1.x, ss.x, z1); z1 = fmaf(p1.y, ss.y, z1);
            z1 = fmaf(p1.z, ss.z, z1); z1 = fmaf(p1.w, ss.w, z1);
        }
        out[((size_t)(b * N_ + n0    )) * INNER_ + h * DH_ + pr] = __float2half_rn(a0 / (z0 + STAB_));
        out[((size_t)(b * N_ + n0 + 4)) * INNER_ + h * DH_ + pr] = __float2half_rn(a1 / (z1 + STAB_));
        __syncthreads();
    }
}

// ---------------- host driver ----------------
extern "C" void kernel_launch(void* const* d_in, const int* in_sizes, int n_in,
                              void* d_out, int out_size)
{
    const int*   tokens  = (const int*)  d_in[0];
    const float* tok_emb = (const float*)d_in[1];
    const float* pos_emb = (const float*)d_in[2];
    const float* Wqkv    = (const float*)d_in[3];
    const float* Wout    = (const float*)d_in[4];
    const float* bout    = (const float*)d_in[5];
    const float* ln1g    = (const float*)d_in[6];
    const float* ln1b    = (const float*)d_in[7];
    const float* ln2g    = (const float*)d_in[8];
    const float* ln2b    = (const float*)d_in[9];
    const float* W1      = (const float*)d_in[10];
    const float* b1      = (const float*)d_in[11];
    const float* W2      = (const float*)d_in[12];
    const float* b2      = (const float*)d_in[13];
    const float* rf      = (const float*)d_in[14];
    float* x = (float*)d_out;

    float *kvpart, *kspart, *kv, *ksum;
    __half *qkv, *ff1, *attnout, *ln, *Wqkvp, *Woutp, *W1p, *W2p;
    cudaGetSymbolAddress((void**)&qkv,     g_qkv);
    cudaGetSymbolAddress((void**)&ff1,     g_ff1);
    cudaGetSymbolAddress((void**)&attnout, g_attnout);
    cudaGetSymbolAddress((void**)&ln,      g_ln);
    cudaGetSymbolAddress((void**)&kvpart,  g_kvpart);
    cudaGetSymbolAddress((void**)&kspart,  g_kspart);
    cudaGetSymbolAddress((void**)&kv,      g_kv);
    cudaGetSymbolAddress((void**)&ksum,    g_ksum);
    cudaGetSymbolAddress((void**)&Wqkvp,   g_Wqkvp);
    cudaGetSymbolAddress((void**)&Woutp,   g_Woutp);
    cudaGetSymbolAddress((void**)&W1p,     g_W1p);
    cudaGetSymbolAddress((void**)&W2p,     g_W2p);

    // dynamic smem opt-in for the KC=64 GEMM (72 KB)
    cudaFuncSetAttribute(gemm_fp16<1, true >, cudaFuncAttributeMaxDynamicSharedMemorySize, SMEM_GEMM);
    cudaFuncSetAttribute(gemm_fp16<2, true >, cudaFuncAttributeMaxDynamicSharedMemorySize, SMEM_GEMM);
    cudaFuncSetAttribute(gemm_fp16<3, false>, cudaFuncAttributeMaxDynamicSharedMemorySize, SMEM_GEMM);

    // weight prep: combined phi weights (q,k) + fp16 conversions (v + rest)
    wcomb_kernel<<<L_ * 2 * H_, 256>>>(Wqkv, rf, Wqkvp);
    for (int l = 0; l < L_; l++) {
        int n4 = INNER_ * D_ / 4;
        wconv_kernel<<<(n4 + 255) / 256, 256>>>(
            Wqkv  + (size_t)l * 3 * INNER_ * D_ + 2 * (size_t)INNER_ * D_,
            Wqkvp + (size_t)l * 3 * INNER_ * D_ + 2 * (size_t)INNER_ * D_, n4);
    }
    {
        int n4;
        n4 = L_*D_*INNER_ / 4; wconv_kernel<<<(n4+255)/256, 256>>>(Wout, Woutp, n4);
        n4 = L_*FF_*D_    / 4; wconv_kernel<<<(n4+255)/256, 256>>>(W1,   W1p,   n4);
        n4 = L_*D_*FF_    / 4; wconv_kernel<<<(n4+255)/256, 256>>>(W2,   W2p,   n4);
    }

    embed_kernel<<<M_, 256>>>(tokens, tok_emb, pos_emb, x);

    for (int l = 0; l < L_; l++) {
        const __half* Wqkv_l = Wqkvp + (size_t)l * 3 * INNER_ * D_;
        const __half* Wout_l = Woutp + (size_t)l * D_ * INNER_;
        const float* bout_l = bout + (size_t)l * D_;
        const float* ln1g_l = ln1g + (size_t)l * D_;
        const float* ln1b_l = ln1b + (size_t)l * D_;
        const float* ln2g_l = ln2g + (size_t)l * D_;
        const float* ln2b_l = ln2b + (size_t)l * D_;
        const __half* W1_l  = W1p  + (size_t)l * FF_ * D_;
        const float* b1_l   = b1   + (size_t)l * FF_;
        const __half* W2_l  = W2p  + (size_t)l * D_ * FF_;
        const float* b2_l   = b2   + (size_t)l * D_;

        // --- attention block ---
        ln_kernel<<<M_, 256>>>(x, ln1g_l, ln1b_l, ln);
        gemm_fp16<1, true><<<dim3(3 * INNER_ / 128, M_ / 128), 256, SMEM_GEMM>>>(
            ln, Wqkv_l, qkv, M_, 3 * INNER_, D_, nullptr, nullptr, 2 * INNER_);
        kvsum_kernel<<<dim3(B_ * H_, NCHUNK_), 256>>>(qkv, kvpart, kspart);
        kvreduce_kernel<<<B_ * H_, 256>>>(kvpart, kspart, kv, ksum);
        attnout_kernel<<<dim3(B_ * H_, N_ / 128), 256>>>(qkv, kv, ksum, attnout);
        gemm_fp16<3, false><<<dim3(D_ / 128, M_ / 128), 256, SMEM_GEMM>>>(
            attnout, Wout_l, x, M_, D_, INNER_, bout_l, x, 0);

        // --- FFN block ---
        ln_kernel<<<M_, 256>>>(x, ln2g_l, ln2b_l, ln);
        gemm_fp16<2, true><<<dim3(FF_ / 128, M_ / 128), 256, SMEM_GEMM>>>(
            ln, W1_l, ff1, M_, FF_, D_, b1_l, nullptr, 0);
        gemm_fp16<3, false><<<dim3(D_ / 128, M_ / 128), 256, SMEM_GEMM>>>(
            ff1, W2_l, x, M_, D_, FF_, b2_l, x, 0);
    }
}

// round 17
// speedup vs baseline: 1.2130x; 1.0280x over previous
#include <cuda_runtime.h>
#include <cuda_fp16.h>
#include <math.h>
#include <stdint.h>

// ---------------- problem constants ----------------
#define B_   2
#define N_   4096
#define D_   1024
#define H_   16
#define DH_  64
#define R_   64
#define L_   6
#define FF_  4096
#define INNER_ 1024
#define M_   (B_*N_)        // 8192 rows
#define EPS_ 1e-5f
#define STAB_ 1e-6f
#define NCHUNK_ 32          // kv-sum chunks per (b,h)

// ---------------- scratch (static device globals; allowed) ----------------
__device__ __align__(16) __half g_qkv[M_ * 3 * INNER_];    // [phi_q | phi_k | v], half
__device__ __align__(16) __half g_ff1[M_ * FF_];
__device__ __align__(16) __half g_attnout[M_ * INNER_];
__device__ __align__(16) __half g_ln[M_ * D_];
__device__ __align__(16) float  g_kvpart[B_*H_*NCHUNK_*R_*DH_];
__device__ __align__(16) float  g_kspart[B_*H_*NCHUNK_*R_];
__device__ __align__(16) float  g_kv[B_*H_*R_*DH_];
__device__ __align__(16) float  g_ksum[B_*H_*R_];
// fp16 weights: g_Wqkvp holds combined [Wphi_q | Wphi_k | Wv]
__device__ __align__(16) __half g_Wqkvp[L_*3*INNER_*D_];
__device__ __align__(16) __half g_Woutp[L_*D_*INNER_];
__device__ __align__(16) __half g_W1p  [L_*FF_*D_];
__device__ __align__(16) __half g_W2p  [L_*D_*FF_];

// ---------------- helpers ----------------
__device__ __forceinline__ uint32_t smem_u32(const void* p) {
    uint32_t a;
    asm("{ .reg .u64 t; cvta.to.shared.u64 t, %1; cvt.u32.u64 %0, t; }" : "=r"(a) : "l"(p));
    return a;
}
__device__ __forceinline__ void cp16(uint32_t s, const void* g) {
    asm volatile("cp.async.cg.shared.global [%0], [%1], 16;\n" :: "r"(s), "l"(g));
}
#define LDSM_X4(r, addr) \
    asm volatile("ldmatrix.sync.aligned.m8n8.x4.shared.b16 {%0,%1,%2,%3}, [%4];" \
        : "=r"((r)[0]), "=r"((r)[1]), "=r"((r)[2]), "=r"((r)[3]) : "r"(addr))

// ---------------- FP16 tensor-core GEMM, 128x128 tile, k-chunk 64 -----------
// (unchanged from round 16)
#define KC    64
#define RSTR  72          // row stride in halves (144B); conflict-free ldmatrix
#define STAGEB (128 * RSTR * 2)          // 18432 B per tile stage
#define SMEM_GEMM (2 * 2 * STAGEB)       // 73728 B

template<int EPI, bool OUTH>
__global__ __launch_bounds__(256) void gemm_fp16(
    const __half* __restrict__ A, const __half* __restrict__ Bw,
    void* __restrict__ Cv, int M, int Nc, int K,
    const float* __restrict__ bias, const float* __restrict__ resid, int relu_lim)
{
    extern __shared__ __align__(16) __half sh[];
    const uint32_t sbase = smem_u32(&sh[0]);

    const int tid  = threadIdx.x;
    const int bm0  = blockIdx.y * 128;
    const int bn0  = blockIdx.x * 128;
    const int warp = tid >> 5;
    const int lane = tid & 31;
    const int wm   = warp >> 2;
    const int wn   = warp & 3;
    const int g8   = lane >> 2;
    const int qid  = lane & 3;

    float c[4][4][4];
    #pragma unroll
    for (int mi = 0; mi < 4; mi++)
        #pragma unroll
        for (int ni = 0; ni < 4; ni++)
            #pragma unroll
            for (int j = 0; j < 4; j++) c[mi][ni][j] = 0.0f;

    const int nIter = K / KC;

    auto load_stage = [&](int it, int buf) {
        const int k0 = it * KC;
        uint32_t sA = sbase + buf * 2 * STAGEB;
        uint32_t sB = sA + STAGEB;
        #pragma unroll
        for (int i = 0; i < 4; i++) {
            int f = i * 256 + tid;
            int row = f >> 3, seg = f & 7;
            cp16(sA + (row * RSTR + seg * 8) * 2,
                 &A[(size_t)(bm0 + row) * K + k0 + seg * 8]);
        }
        #pragma unroll
        for (int i = 0; i < 4; i++) {
            int f = i * 256 + tid;
            int row = f >> 3, seg = f & 7;
            cp16(sB + (row * RSTR + seg * 8) * 2,
                 &Bw[(size_t)(bn0 + row) * K + k0 + seg * 8]);
        }
        asm volatile("cp.async.commit_group;\n" ::: "memory");
    };

    load_stage(0, 0);

    for (int it = 0; it < nIter; it++) {
        int buf = it & 1;
        if (it + 1 < nIter) {
            load_stage(it + 1, buf ^ 1);
            asm volatile("cp.async.wait_group 1;\n" ::: "memory");
        } else {
            asm volatile("cp.async.wait_group 0;\n" ::: "memory");
        }
        __syncthreads();

        uint32_t sA = sbase + buf * 2 * STAGEB;
        uint32_t sB = sA + STAGEB;

        #pragma unroll
        for (int ks = 0; ks < KC; ks += 16) {
            uint32_t af[4][4];
            #pragma unroll
            for (int mi = 0; mi < 4; mi++) {
                int m0 = wm * 64 + mi * 16;
                uint32_t addr = sA + (((m0 + (lane & 15)) * RSTR) + ks + ((lane >> 4) << 3)) * 2;
                LDSM_X4(af[mi], addr);
            }
            uint32_t bf[2][4];
            #pragma unroll
            for (int nb = 0; nb < 2; nb++) {
                int n0 = wn * 32 + nb * 16;
                uint32_t addr = sB + (((n0 + (lane & 7) + ((lane >> 4) << 3)) * RSTR)
                                      + ks + (((lane >> 3) & 1) << 3)) * 2;
                LDSM_X4(bf[nb], addr);
            }
            #pragma unroll
            for (int mi = 0; mi < 4; mi++)
                #pragma unroll
                for (int ni = 0; ni < 4; ni++) {
                    uint32_t b0 = bf[ni >> 1][(ni & 1) * 2];
                    uint32_t b1 = bf[ni >> 1][(ni & 1) * 2 + 1];
                    asm volatile(
                        "mma.sync.aligned.m16n8k16.row.col.f32.f16.f16.f32 "
                        "{%0,%1,%2,%3}, {%4,%5,%6,%7}, {%8,%9}, {%0,%1,%2,%3};\n"
                        : "+f"(c[mi][ni][0]), "+f"(c[mi][ni][1]),
                          "+f"(c[mi][ni][2]), "+f"(c[mi][ni][3])
                        : "r"(af[mi][0]), "r"(af[mi][1]), "r"(af[mi][2]), "r"(af[mi][3]),
                          "r"(b0), "r"(b1));
                }
        }
        __syncthreads();
    }

    // ---- epilogue ----
    #pragma unroll
    for (int mi = 0; mi < 4; mi++) {
        int row0 = bm0 + wm * 64 + mi * 16 + g8;
        int row1 = row0 + 8;
        #pragma unroll
        for (int ni = 0; ni < 4; ni++) {
            int col = bn0 + wn * 32 + ni * 8 + qid * 2;
            float o0 = c[mi][ni][0], o1 = c[mi][ni][1];
            float o2 = c[mi][ni][2], o3 = c[mi][ni][3];
            if (EPI == 1) {
                if (col < relu_lim) {
                    o0 = fmaxf(o0, 0.0f); o1 = fmaxf(o1, 0.0f);
                    o2 = fmaxf(o2, 0.0f); o3 = fmaxf(o3, 0.0f);
                }
            }
            if (EPI >= 2) {
                float b0 = bias[col], b1 = bias[col + 1];
                o0 += b0; o1 += b1; o2 += b0; o3 += b1;
            }
            if (EPI == 2) {
                o0 = 0.5f * o0 * (1.0f + erff(o0 * 0.70710678118654752f));
                o1 = 0.5f * o1 * (1.0f + erff(o1 * 0.70710678118654752f));
                o2 = 0.5f * o2 * (1.0f + erff(o2 * 0.70710678118654752f));
                o3 = 0.5f * o3 * (1.0f + erff(o3 * 0.70710678118654752f));
            }
            if (EPI == 3) {
                float2 r0 = *(const float2*)&resid[(size_t)row0 * Nc + col];
                float2 r1 = *(const float2*)&resid[(size_t)row1 * Nc + col];
                o0 += r0.x; o1 += r0.y; o2 += r1.x; o3 += r1.y;
            }
            if (OUTH) {
                __half* C = (__half*)Cv;
                *(__half2*)&C[(size_t)row0 * Nc + col] = __floats2half2_rn(o0, o1);
                *(__half2*)&C[(size_t)row1 * Nc + col] = __floats2half2_rn(o2, o3);
            } else {
                float* C = (float*)Cv;
                *(float2*)&C[(size_t)row0 * Nc + col] = make_float2(o0, o1);
                *(float2*)&C[(size_t)row1 * Nc + col] = make_float2(o2, o3);
            }
        }
    }
}

// ---------------- weight convert: fp32 -> fp16 ----------------
__global__ __launch_bounds__(256) void wconv_kernel(
    const float* __restrict__ in, __half* __restrict__ out, int n4)
{
    int i = blockIdx.x * 256 + threadIdx.x;
    if (i >= n4) return;
    float4 v = *(const float4*)&in[(size_t)i * 4];
    *(__half2*)&out[(size_t)i * 4]     = __floats2half2_rn(v.x, v.y);
    *(__half2*)&out[(size_t)i * 4 + 2] = __floats2half2_rn(v.z, v.w);
}

// ---------------- combined phi weights ----------------
__global__ __launch_bounds__(256) void wcomb_kernel(
    const float* __restrict__ Wqkv, const float* __restrict__ rf,
    __half* __restrict__ out)
{
    __shared__ float rfs[64 * 64];
    __shared__ float wt[64][64];
    int blk = blockIdx.x;
    int l = blk >> 5, rest = blk & 31;
    int qk = rest >> 4, h = rest & 15;
    int tid = threadIdx.x;

    const float* W   = Wqkv + ((size_t)l * 3 * INNER_ + qk * INNER_ + h * DH_) * D_;
    const float* rfh = rf + ((size_t)(l * H_ + h)) * DH_ * R_;
    __half* o = out + (size_t)l * 3 * INNER_ * D_ + (size_t)(qk * INNER_ + h * R_) * D_;

    #pragma unroll
    for (int i = 0; i < 16; i++) rfs[tid + i * 256] = rfh[tid + i * 256];
    __syncthreads();

    int r  = tid >> 2;
    int j0 = (tid & 3) << 4;
    for (int ct = 0; ct < 16; ct++) {
        #pragma unroll
        for (int i = 0; i < 16; i++) {
            int f = tid + i * 256;
            int d = f >> 6, cc = f & 63;
            wt[d][cc] = W[(size_t)d * D_ + ct * 64 + cc];
        }
        __syncthreads();
        float acc[16];
        #pragma unroll
        for (int j = 0; j < 16; j++) acc[j] = 0.0f;
        for (int d = 0; d < 64; d++) {
            float p = rfs[d * 64 + r];
            #pragma unroll
            for (int j = 0; j < 16; j++) acc[j] = fmaf(p, wt[d][j0 + j], acc[j]);
        }
        #pragma unroll
        for (int j = 0; j < 16; j += 2)
            *(__half2*)&o[(size_t)r * D_ + ct * 64 + j0 + j] =
                __floats2half2_rn(acc[j], acc[j + 1]);
        __syncthreads();
    }
}

// ---------------- embedding ----------------
__global__ __launch_bounds__(256) void embed_kernel(
    const int* __restrict__ tokens, const float* __restrict__ te,
    const float* __restrict__ pe, float* __restrict__ x)
{
    int row = blockIdx.x;
    int tid = threadIdx.x;
    int n = row & (N_ - 1);
    int tok = tokens[row];
    float4 a = *(const float4*)&te[(size_t)tok * D_ + tid * 4];
    float4 p = *(const float4*)&pe[(size_t)n * D_ + tid * 4];
    a.x += p.x; a.y += p.y; a.z += p.z; a.w += p.w;
    *(float4*)&x[(size_t)row * D_ + tid * 4] = a;
}

// ---------------- LayerNorm: warp-per-row, no barriers ----------------------
__global__ __launch_bounds__(256) void ln_kernel(
    const float* __restrict__ x, const float* __restrict__ lng,
    const float* __restrict__ lnb, __half* __restrict__ h)
{
    int warp = threadIdx.x >> 5, lane = threadIdx.x & 31;
    int row = blockIdx.x * 8 + warp;
    const float* xr = x + (size_t)row * D_;
    float4 v[8];
    float s = 0.0f;
    #pragma unroll
    for (int k = 0; k < 8; k++) {
        v[k] = *(const float4*)&xr[k * 128 + lane * 4];
        s += v[k].x + v[k].y + v[k].z + v[k].w;
    }
    #pragma unroll
    for (int o = 16; o > 0; o >>= 1) s += __shfl_xor_sync(0xffffffffu, s, o);
    float mu = s * (1.0f / D_);
    float var = 0.0f;
    #pragma unroll
    for (int k = 0; k < 8; k++) {
        float dx = v[k].x - mu, dy = v[k].y - mu, dz = v[k].z - mu, dw = v[k].w - mu;
        var += dx*dx + dy*dy + dz*dz + dw*dw;
    }
    #pragma unroll
    for (int o = 16; o > 0; o >>= 1) var += __shfl_xor_sync(0xffffffffu, var, o);
    float rs = rsqrtf(var * (1.0f / D_) + EPS_);
    __half* hr = h + (size_t)row * D_;
    #pragma unroll
    for (int k = 0; k < 8; k++) {
        int cc = k * 128 + lane * 4;
        float4 gg = *(const float4*)&lng[cc];
        float4 bb = *(const float4*)&lnb[cc];
        *(__half2*)&hr[cc]     = __floats2half2_rn((v[k].x - mu) * rs * gg.x + bb.x,
                                                   (v[k].y - mu) * rs * gg.y + bb.y);
        *(__half2*)&hr[cc + 2] = __floats2half2_rn((v[k].z - mu) * rs * gg.z + bb.z,
                                                   (v[k].w - mu) * rs * gg.w + bb.w);
    }
}

// ---------------- kv-sum (unchanged from round 16) --------------------------
__global__ __launch_bounds__(256) void kvsum_kernel(
    const __half* __restrict__ qkvh,
    float* __restrict__ kvpart, float* __restrict__ kspart)
{
    __shared__ float vsm[8][64];
    __shared__ float phism[8][64];
    int tid = threadIdx.x;
    int bh = blockIdx.x;
    int b = bh >> 4, h = bh & 15;
    int chunk = blockIdx.y;

    int prow = tid >> 6, pr = tid & 63;
    float acc[16];
    #pragma unroll
    for (int j = 0; j < 16; j++) acc[j] = 0.0f;
    int my_r  = tid >> 2;
    int my_d0 = (tid & 3) << 4;
    float kslocal = 0.0f;
    int nbase = chunk * 128;

    for (int gidx = 0; gidx < 16; gidx++) {
        int n0 = nbase + gidx * 8 + prow;
        size_t base0 = ((size_t)(b * N_ + n0)) * (3 * INNER_) + h * DH_;
        size_t base1 = base0 + (size_t)4 * (3 * INNER_);
        float p0 = __half2float(qkvh[base0 + INNER_ + pr]);
        float p1 = __half2float(qkvh[base1 + INNER_ + pr]);
        phism[prow    ][pr] = p0;
        phism[prow + 4][pr] = p1;
        vsm[prow    ][pr] = __half2float(qkvh[base0 + 2 * INNER_ + pr]);
        vsm[prow + 4][pr] = __half2float(qkvh[base1 + 2 * INNER_ + pr]);
        kslocal += p0 + p1;
        __syncthreads();
        #pragma unroll
        for (int rr = 0; rr < 8; rr++) {
            float p = phism[rr][my_r];
            float4 v0 = *(const float4*)&vsm[rr][my_d0];
            float4 v1 = *(const float4*)&vsm[rr][my_d0 + 4];
            float4 v2 = *(const float4*)&vsm[rr][my_d0 + 8];
            float4 v3 = *(const float4*)&vsm[rr][my_d0 + 12];
            acc[0]  = fmaf(p, v0.x, acc[0]);  acc[1]  = fmaf(p, v0.y, acc[1]);
            acc[2]  = fmaf(p, v0.z, acc[2]);  acc[3]  = fmaf(p, v0.w, acc[3]);
            acc[4]  = fmaf(p, v1.x, acc[4]);  acc[5]  = fmaf(p, v1.y, acc[5]);
            acc[6]  = fmaf(p, v1.z, acc[6]);  acc[7]  = fmaf(p, v1.w, acc[7]);
            acc[8]  = fmaf(p, v2.x, acc[8]);  acc[9]  = fmaf(p, v2.y, acc[9]);
            acc[10] = fmaf(p, v2.z, acc[10]); acc[11] = fmaf(p, v2.w, acc[11]);
            acc[12] = fmaf(p, v3.x, acc[12]); acc[13] = fmaf(p, v3.y, acc[13]);
            acc[14] = fmaf(p, v3.z, acc[14]); acc[15] = fmaf(p, v3.w, acc[15]);
        }
        __syncthreads();
    }

    float* kvp = kvpart + ((size_t)(bh * NCHUNK_ + chunk)) * (R_ * DH_);
    #pragma unroll
    for (int j = 0; j < 16; j++) kvp[my_r * 64 + my_d0 + j] = acc[j];

    phism[prow][pr] = kslocal;
    __syncthreads();
    if (tid < 64) {
        float s = phism[0][tid] + phism[1][tid] + phism[2][tid] + phism[3][tid];
        kspart[(bh * NCHUNK_ + chunk) * R_ + tid] = s;
    }
}

__global__ __launch_bounds__(256) void kvreduce_kernel(
    const float* __restrict__ kvpart, const float* __restrict__ kspart,
    float* __restrict__ kv, float* __restrict__ ks)
{
    int bh = blockIdx.x, tid = threadIdx.x;
    for (int i = tid; i < R_ * DH_; i += 256) {
        float s = 0.0f;
        #pragma unroll
        for (int c = 0; c < NCHUNK_; c++)
            s += kvpart[((size_t)(bh * NCHUNK_ + c)) * (R_ * DH_) + i];
        kv[(size_t)bh * (R_ * DH_) + i] = s;
    }
    if (tid < 64) {
        float s = 0.0f;
        #pragma unroll
        for (int c = 0; c < NCHUNK_; c++) s += kspart[(bh * NCHUNK_ + c) * R_ + tid];
        ks[bh * R_ + tid] = s;
    }
}

// ---------------- attention out: normalizer hoisted to warp phase -----------
__global__ __launch_bounds__(256) void attnout_kernel(
    const __half* __restrict__ qkvh,
    const float* __restrict__ kv, const float* __restrict__ ksum,
    __half* __restrict__ out)
{
    __shared__ float kvT[64 * 68];
    __shared__ float kssm[R_];
    __shared__ float phism[8][64];
    __shared__ float zsm[8];
    int tid = threadIdx.x;
    int bh = blockIdx.x;
    int b = bh >> 4, h = bh & 15;
    int tile = blockIdx.y;

    int prow = tid >> 6, pr = tid & 63;
    int wrow = tid >> 5, lane = tid & 31;
    const float* kvg = kv + (size_t)bh * (R_ * DH_);
    for (int i = tid; i < R_ * DH_; i += 256) {
        int r = i >> 6, d = i & 63;
        kvT[d * 68 + r] = kvg[i];
    }
    if (tid < 64) kssm[tid] = ksum[bh * R_ + tid];
    __syncthreads();

    int nbase = tile * 128;
    for (int gidx = 0; gidx < 16; gidx++) {
        int n0 = nbase + gidx * 8 + prow;
        size_t base0 = ((size_t)(b * N_ + n0)) * (3 * INNER_) + h * DH_;
        size_t base1 = base0 + (size_t)4 * (3 * INNER_);
        phism[prow    ][pr] = __half2float(qkvh[base0 + pr]);
        phism[prow + 4][pr] = __half2float(qkvh[base1 + pr]);
        __syncthreads();
        // normalizer: warp w computes z for row w (conflict-free lane-strided reads)
        {
            float zp = fmaf(phism[wrow][lane], kssm[lane],
                            phism[wrow][lane + 32] * kssm[lane + 32]);
            #pragma unroll
            for (int o = 16; o > 0; o >>= 1) zp += __shfl_xor_sync(0xffffffffu, zp, o);
            if (lane == 0) zsm[wrow] = zp;
        }
        __syncthreads();
        float a0 = 0.0f, a1 = 0.0f;
        #pragma unroll
        for (int rc = 0; rc < 16; rc++) {
            float4 p0 = *(const float4*)&phism[prow    ][rc * 4];
            float4 p1 = *(const float4*)&phism[prow + 4][rc * 4];
            float4 kk = *(const float4*)&kvT[pr * 68 + rc * 4];
            a0 = fmaf(p0.x, kk.x, a0); a0 = fmaf(p0.y, kk.y, a0);
            a0 = fmaf(p0.z, kk.z, a0); a0 = fmaf(p0.w, kk.w, a0);
            a1 = fmaf(p1.x, kk.x, a1); a1 = fmaf(p1.y, kk.y, a1);
            a1 = fmaf(p1.z, kk.z, a1); a1 = fmaf(p1.w, kk.w, a1);
        }
        float z0 = zsm[prow], z1 = zsm[prow + 4];
        out[((size_t)(b * N_ + n0    )) * INNER_ + h * DH_ + pr] = __float2half_rn(a0 / (z0 + STAB_));
        out[((size_t)(b * N_ + n0 + 4)) * INNER_ + h * DH_ + pr] = __float2half_rn(a1 / (z1 + STAB_));
        __syncthreads();
    }
}

// ---------------- host driver ----------------
extern "C" void kernel_launch(void* const* d_in, const int* in_sizes, int n_in,
                              void* d_out, int out_size)
{
    const int*   tokens  = (const int*)  d_in[0];
    const float* tok_emb = (const float*)d_in[1];
    const float* pos_emb = (const float*)d_in[2];
    const float* Wqkv    = (const float*)d_in[3];
    const float* Wout    = (const float*)d_in[4];
    const float* bout    = (const float*)d_in[5];
    const float* ln1g    = (const float*)d_in[6];
    const float* ln1b    = (const float*)d_in[7];
    const float* ln2g    = (const float*)d_in[8];
    const float* ln2b    = (const float*)d_in[9];
    const float* W1      = (const float*)d_in[10];
    const float* b1      = (const float*)d_in[11];
    const float* W2      = (const float*)d_in[12];
    const float* b2      = (const float*)d_in[13];
    const float* rf      = (const float*)d_in[14];
    float* x = (float*)d_out;

    float *kvpart, *kspart, *kv, *ksum;
    __half *qkv, *ff1, *attnout, *ln, *Wqkvp, *Woutp, *W1p, *W2p;
    cudaGetSymbolAddress((void**)&qkv,     g_qkv);
    cudaGetSymbolAddress((void**)&ff1,     g_ff1);
    cudaGetSymbolAddress((void**)&attnout, g_attnout);
    cudaGetSymbolAddress((void**)&ln,      g_ln);
    cudaGetSymbolAddress((void**)&kvpart,  g_kvpart);
    cudaGetSymbolAddress((void**)&kspart,  g_kspart);
    cudaGetSymbolAddress((void**)&kv,      g_kv);
    cudaGetSymbolAddress((void**)&ksum,    g_ksum);
    cudaGetSymbolAddress((void**)&Wqkvp,   g_Wqkvp);
    cudaGetSymbolAddress((void**)&Woutp,   g_Woutp);
    cudaGetSymbolAddress((void**)&W1p,     g_W1p);
    cudaGetSymbolAddress((void**)&W2p,     g_W2p);

    // dynamic smem opt-in for the KC=64 GEMM (72 KB)
    cudaFuncSetAttribute(gemm_fp16<1, true >, cudaFuncAttributeMaxDynamicSharedMemorySize, SMEM_GEMM);
    cudaFuncSetAttribute(gemm_fp16<2, true >, cudaFuncAttributeMaxDynamicSharedMemorySize, SMEM_GEMM);
    cudaFuncSetAttribute(gemm_fp16<3, false>, cudaFuncAttributeMaxDynamicSharedMemorySize, SMEM_GEMM);

    // weight prep: combined phi weights (q,k) + fp16 conversions (v + rest)
    wcomb_kernel<<<L_ * 2 * H_, 256>>>(Wqkv, rf, Wqkvp);
    for (int l = 0; l < L_; l++) {
        int n4 = INNER_ * D_ / 4;
        wconv_kernel<<<(n4 + 255) / 256, 256>>>(
            Wqkv  + (size_t)l * 3 * INNER_ * D_ + 2 * (size_t)INNER_ * D_,
            Wqkvp + (size_t)l * 3 * INNER_ * D_ + 2 * (size_t)INNER_ * D_, n4);
    }
    {
        int n4;
        n4 = L_*D_*INNER_ / 4; wconv_kernel<<<(n4+255)/256, 256>>>(Wout, Woutp, n4);
        n4 = L_*FF_*D_    / 4; wconv_kernel<<<(n4+255)/256, 256>>>(W1,   W1p,   n4);
        n4 = L_*D_*FF_    / 4; wconv_kernel<<<(n4+255)/256, 256>>>(W2,   W2p,   n4);
    }

    embed_kernel<<<M_, 256>>>(tokens, tok_emb, pos_emb, x);

    for (int l = 0; l < L_; l++) {
        const __half* Wqkv_l = Wqkvp + (size_t)l * 3 * INNER_ * D_;
        const __half* Wout_l = Woutp + (size_t)l * D_ * INNER_;
        const float* bout_l = bout + (size_t)l * D_;
        const float* ln1g_l = ln1g + (size_t)l * D_;
        const float* ln1b_l = ln1b + (size_t)l * D_;
        const float* ln2g_l = ln2g + (size_t)l * D_;
        const float* ln2b_l = ln2b + (size_t)l * D_;
        const __half* W1_l  = W1p  + (size_t)l * FF_ * D_;
        const float* b1_l   = b1   + (size_t)l * FF_;
        const __half* W2_l  = W2p  + (size_t)l * D_ * FF_;
        const float* b2_l   = b2   + (size_t)l * D_;

        // --- attention block ---
        ln_kernel<<<M_ / 8, 256>>>(x, ln1g_l, ln1b_l, ln);
        gemm_fp16<1, true><<<dim3(3 * INNER_ / 128, M_ / 128), 256, SMEM_GEMM>>>(
            ln, Wqkv_l, qkv, M_, 3 * INNER_, D_, nullptr, nullptr, 2 * INNER_);
        kvsum_kernel<<<dim3(B_ * H_, NCHUNK_), 256>>>(qkv, kvpart, kspart);
        kvreduce_kernel<<<B_ * H_, 256>>>(kvpart, kspart, kv, ksum);
        attnout_kernel<<<dim3(B_ * H_, N_ / 128), 256>>>(qkv, kv, ksum, attnout);
        gemm_fp16<3, false><<<dim3(D_ / 128, M_ / 128), 256, SMEM_GEMM>>>(
            attnout, Wout_l, x, M_, D_, INNER_, bout_l, x, 0);

        // --- FFN block ---
        ln_kernel<<<M_ / 8, 256>>>(x, ln2g_l, ln2b_l, ln);
        gemm_fp16<2, true><<<dim3(FF_ / 128, M_ / 128), 256, SMEM_GEMM>>>(
            ln, W1_l, ff1, M_, FF_, D_, b1_l, nullptr, 0);
        gemm_fp16<3, false><<<dim3(D_ / 128, M_ / 128), 256, SMEM_GEMM>>>(
            ff1, W2_l, x, M_, D_, FF_, b2_l, x, 0);
    }
}